// round 7
// baseline (speedup 1.0000x reference)
#include <cuda_runtime.h>
#include <math.h>

#define BB 8
#define TT 256
#define SS 256
#define HH 512
#define TQ 4

// Scratch: projected tensors (4 MB each). Device globals — no allocation.
__device__ float g_enc_f[BB * SS * HH];
__device__ float g_qry_f[BB * TT * HH];

// ---------------------------------------------------------------------------
// tf32 helpers
// ---------------------------------------------------------------------------
__device__ __forceinline__ unsigned f2tf32(float x) {
    unsigned r;
    asm("cvt.rna.tf32.f32 %0, %1;" : "=r"(r) : "f"(x));
    return r;
}

__device__ __forceinline__ void mma_tf32(float* c, const unsigned* a, const unsigned* b) {
    asm("mma.sync.aligned.m16n8k8.row.col.f32.tf32.tf32.f32 "
        "{%0,%1,%2,%3},{%4,%5,%6,%7},{%8,%9},{%0,%1,%2,%3};"
        : "+f"(c[0]), "+f"(c[1]), "+f"(c[2]), "+f"(c[3])
        : "r"(a[0]), "r"(a[1]), "r"(a[2]), "r"(a[3]), "r"(b[0]), "r"(b[1]));
}

// ---------------------------------------------------------------------------
// Fused projection GEMM (tensor cores, tf32):
//   rows [0,2048):    g_enc_f[n,o] = sum_h enc[n,h]   * W_h[o,h]
//   rows [2048,4096): g_qry_f[n,o] = sum_h query[n,h] * W_s[o,h]
// ---------------------------------------------------------------------------
__global__ __launch_bounds__(256)
void gemm_tf32_kernel(const float* __restrict__ enc,
                      const float* __restrict__ qry,
                      const float* __restrict__ W_h,
                      const float* __restrict__ W_s) {
    int tid  = threadIdx.x;
    int lane = tid & 31, warp = tid >> 5;
    int g  = lane >> 2;      // groupID 0..7
    int tg = lane & 3;       // thread-in-group 0..3
    int warp_m = warp & 3;   // 0..3
    int warp_n = warp >> 2;  // 0..1

    int m_blk = blockIdx.y * 128;          // global fused-row base
    int n_blk = blockIdx.x * 64;

    const float* X;
    const float* W;
    float*       Y;
    if (m_blk < 2048) {
        X = enc + (size_t)m_blk * HH;
        W = W_h;
        Y = g_enc_f + (size_t)m_blk * HH;
    } else {
        X = qry + (size_t)(m_blk - 2048) * HH;
        W = W_s;
        Y = g_qry_f + (size_t)(m_blk - 2048) * HH;
    }

    int m_base = warp_m * 32;              // local row base within block tile
    int n_base = n_blk + warp_n * 32;      // global col base

    float acc[2][4][4];
    #pragma unroll
    for (int i = 0; i < 2; i++)
        #pragma unroll
        for (int j = 0; j < 4; j++)
            #pragma unroll
            for (int c = 0; c < 4; c++) acc[i][j][c] = 0.f;

    for (int k0 = 0; k0 < HH; k0 += 8) {
        unsigned a[2][4], b[4][2];
        #pragma unroll
        for (int i = 0; i < 2; i++) {
            const float* xp = X + (size_t)(m_base + i * 16 + g) * HH + k0 + tg;
            a[i][0] = f2tf32(xp[0]);
            a[i][1] = f2tf32(xp[8 * HH]);
            a[i][2] = f2tf32(xp[4]);
            a[i][3] = f2tf32(xp[8 * HH + 4]);
        }
        #pragma unroll
        for (int j = 0; j < 4; j++) {
            const float* wp = W + (size_t)(n_base + j * 8 + g) * HH + k0 + tg;
            b[j][0] = f2tf32(wp[0]);
            b[j][1] = f2tf32(wp[4]);
        }
        #pragma unroll
        for (int i = 0; i < 2; i++)
            #pragma unroll
            for (int j = 0; j < 4; j++)
                mma_tf32(acc[i][j], a[i], b[j]);
    }

    #pragma unroll
    for (int i = 0; i < 2; i++) {
        #pragma unroll
        for (int j = 0; j < 4; j++) {
            int row0 = m_base + i * 16 + g;
            int col  = n_base + j * 8 + 2 * tg;
            Y[(size_t)row0 * HH + col]           = acc[i][j][0];
            Y[(size_t)row0 * HH + col + 1]       = acc[i][j][1];
            Y[(size_t)(row0 + 8) * HH + col]     = acc[i][j][2];
            Y[(size_t)(row0 + 8) * HH + col + 1] = acc[i][j][3];
        }
    }
}

__device__ __forceinline__ float fast_tanh(float x) {
    float r;
    asm("tanh.approx.f32 %0, %1;" : "=f"(r) : "f"(x));
    return r;
}

// ---------------------------------------------------------------------------
// Fused attention, TQ=4 queries per block: scores + softmax + AV.
// Low-register score loop (k-outer, unroll 4) so 4 blocks/SM fit -> ~44% occ.
// ---------------------------------------------------------------------------
__global__ __launch_bounds__(256, 4)
void attn_kernel(const float* __restrict__ enc,
                 const int* __restrict__ src_len,
                 const float* __restrict__ v,
                 float* __restrict__ out) {
    __shared__ float q_s[TQ][HH];   //  8 KB
    __shared__ float v_s[HH];       //  2 KB
    __shared__ float w_s[TQ][SS];   //  4 KB

    int b  = blockIdx.y;
    int t0 = blockIdx.x * TQ;
    int tid = threadIdx.x;
    int lane = tid & 31, warp = tid >> 5;

    {
        const float* src = g_qry_f + ((size_t)b * TT + t0) * HH;
        float* dst = &q_s[0][0];
        for (int i = tid; i < TQ * HH; i += 256) dst[i] = src[i];
        for (int h = tid; h < HH; h += 256) v_s[h] = v[h];
    }
    __syncthreads();

    int len = src_len[b];   // int32, in [1, S]

    // ---- scores: warp-per-s, skip masked s entirely
    for (int s = warp; s < len; s += 8) {
        const float* __restrict__ e =
            g_enc_f + ((size_t)b * SS + s) * HH + lane;
        float acc0 = 0.f, acc1 = 0.f, acc2 = 0.f, acc3 = 0.f;
        #pragma unroll 4
        for (int k = 0; k < 16; k++) {
            float er = e[32 * k];
            float vv = v_s[lane + 32 * k];
            acc0 = fmaf(vv, fast_tanh(er + q_s[0][lane + 32 * k]), acc0);
            acc1 = fmaf(vv, fast_tanh(er + q_s[1][lane + 32 * k]), acc1);
            acc2 = fmaf(vv, fast_tanh(er + q_s[2][lane + 32 * k]), acc2);
            acc3 = fmaf(vv, fast_tanh(er + q_s[3][lane + 32 * k]), acc3);
        }
        #pragma unroll
        for (int o = 16; o > 0; o >>= 1) {
            acc0 += __shfl_xor_sync(0xffffffffu, acc0, o);
            acc1 += __shfl_xor_sync(0xffffffffu, acc1, o);
            acc2 += __shfl_xor_sync(0xffffffffu, acc2, o);
            acc3 += __shfl_xor_sync(0xffffffffu, acc3, o);
        }
        if (lane == 0) {
            w_s[0][s] = acc0;
            w_s[1][s] = acc1;
            w_s[2][s] = acc2;
            w_s[3][s] = acc3;
        }
    }
    __syncthreads();

    // ---- softmax: warp tq (< TQ) owns query row tq
    if (warp < TQ) {
        int tq = warp;
        float vals[SS / 32];
        float m = -INFINITY;
        #pragma unroll
        for (int j = 0; j < SS / 32; j++) {
            int s = lane + 32 * j;
            float x = (s < len) ? w_s[tq][s] : -INFINITY;
            vals[j] = x;
            m = fmaxf(m, x);
        }
        #pragma unroll
        for (int o = 16; o > 0; o >>= 1)
            m = fmaxf(m, __shfl_xor_sync(0xffffffffu, m, o));
        float sum = 0.f;
        #pragma unroll
        for (int j = 0; j < SS / 32; j++) {
            int s = lane + 32 * j;
            float ex = (s < len) ? __expf(vals[j] - m) : 0.f;
            vals[j] = ex;
            sum += ex;
        }
        #pragma unroll
        for (int o = 16; o > 0; o >>= 1)
            sum += __shfl_xor_sync(0xffffffffu, sum, o);
        float inv = 1.f / sum;
        #pragma unroll
        for (int j = 0; j < SS / 32; j++)
            w_s[tq][lane + 32 * j] = vals[j] * inv;
    }
    __syncthreads();

    // ---- AV: thread owns h = 2*tid, 2*tid+1 (float2), all TQ queries
    {
        float2 acc[TQ];
        #pragma unroll
        for (int tq = 0; tq < TQ; tq++) acc[tq] = make_float2(0.f, 0.f);

        const float2* __restrict__ eb =
            (const float2*)(enc + (size_t)b * SS * HH) + tid;
        for (int s = 0; s < len; s++) {
            float2 ev = eb[(size_t)s * (HH / 2)];
            #pragma unroll
            for (int tq = 0; tq < TQ; tq++) {
                float w = w_s[tq][s];
                acc[tq].x = fmaf(w, ev.x, acc[tq].x);
                acc[tq].y = fmaf(w, ev.y, acc[tq].y);
            }
        }
        #pragma unroll
        for (int tq = 0; tq < TQ; tq++) {
            float2* op = (float2*)(out + ((size_t)b * TT + t0 + tq) * HH) + tid;
            *op = acc[tq];
        }
    }
}

extern "C" void kernel_launch(void* const* d_in, const int* in_sizes, int n_in,
                              void* d_out, int out_size) {
    const float* query   = (const float*)d_in[0];
    const float* enc     = (const float*)d_in[1];
    const int*   src_len = (const int*)d_in[2];
    const float* W_h     = (const float*)d_in[3];
    const float* W_s     = (const float*)d_in[4];
    const float* v       = (const float*)d_in[5];
    float*       out     = (float*)d_out;

    dim3 ggrd(HH / 64, (2 * BB * SS) / 128);   // (8, 32) = 256 blocks
    gemm_tf32_kernel<<<ggrd, 256>>>(enc, query, W_h, W_s);

    dim3 agrd(TT / TQ, BB);                    // (64, 8) = 512 blocks
    attn_kernel<<<agrd, 256>>>(enc, src_len, v, out);
}

// round 8
// speedup vs baseline: 1.7085x; 1.7085x over previous
#include <cuda_runtime.h>
#include <math.h>

#define BB 8
#define TT 256
#define SS 256
#define HH 512
#define TQ 8
#define SCHUNK 64

// Scratch (device globals — no allocation).
__device__ float g_enc_f[BB * SS * HH];
__device__ float g_qry_f[BB * TT * HH];
__device__ float g_scores[BB * TT * SS];

// ---------------------------------------------------------------------------
// tf32 helpers
// ---------------------------------------------------------------------------
__device__ __forceinline__ unsigned f2tf32(float x) {
    unsigned r;
    asm("cvt.rna.tf32.f32 %0, %1;" : "=r"(r) : "f"(x));
    return r;
}

__device__ __forceinline__ void mma_tf32(float* c, const unsigned* a, const unsigned* b) {
    asm("mma.sync.aligned.m16n8k8.row.col.f32.tf32.tf32.f32 "
        "{%0,%1,%2,%3},{%4,%5,%6,%7},{%8,%9},{%0,%1,%2,%3};"
        : "+f"(c[0]), "+f"(c[1]), "+f"(c[2]), "+f"(c[3])
        : "r"(a[0]), "r"(a[1]), "r"(a[2]), "r"(a[3]), "r"(b[0]), "r"(b[1]));
}

// ---------------------------------------------------------------------------
// Fused projection GEMM (tf32 tensor cores):
//   rows [0,2048):    g_enc_f = enc @ W_h^T
//   rows [2048,4096): g_qry_f = query @ W_s^T
// ---------------------------------------------------------------------------
__global__ __launch_bounds__(256)
void gemm_tf32_kernel(const float* __restrict__ enc,
                      const float* __restrict__ qry,
                      const float* __restrict__ W_h,
                      const float* __restrict__ W_s) {
    int tid  = threadIdx.x;
    int lane = tid & 31, warp = tid >> 5;
    int g  = lane >> 2;
    int tg = lane & 3;
    int warp_m = warp & 3;
    int warp_n = warp >> 2;

    int m_blk = blockIdx.y * 128;
    int n_blk = blockIdx.x * 64;

    const float* X;
    const float* W;
    float*       Y;
    if (m_blk < 2048) {
        X = enc + (size_t)m_blk * HH;
        W = W_h;
        Y = g_enc_f + (size_t)m_blk * HH;
    } else {
        X = qry + (size_t)(m_blk - 2048) * HH;
        W = W_s;
        Y = g_qry_f + (size_t)(m_blk - 2048) * HH;
    }

    int m_base = warp_m * 32;
    int n_base = n_blk + warp_n * 32;

    float acc[2][4][4];
    #pragma unroll
    for (int i = 0; i < 2; i++)
        #pragma unroll
        for (int j = 0; j < 4; j++)
            #pragma unroll
            for (int c = 0; c < 4; c++) acc[i][j][c] = 0.f;

    for (int k0 = 0; k0 < HH; k0 += 8) {
        unsigned a[2][4], b[4][2];
        #pragma unroll
        for (int i = 0; i < 2; i++) {
            const float* xp = X + (size_t)(m_base + i * 16 + g) * HH + k0 + tg;
            a[i][0] = f2tf32(xp[0]);
            a[i][1] = f2tf32(xp[8 * HH]);
            a[i][2] = f2tf32(xp[4]);
            a[i][3] = f2tf32(xp[8 * HH + 4]);
        }
        #pragma unroll
        for (int j = 0; j < 4; j++) {
            const float* wp = W + (size_t)(n_base + j * 8 + g) * HH + k0 + tg;
            b[j][0] = f2tf32(wp[0]);
            b[j][1] = f2tf32(wp[4]);
        }
        #pragma unroll
        for (int i = 0; i < 2; i++)
            #pragma unroll
            for (int j = 0; j < 4; j++)
                mma_tf32(acc[i][j], a[i], b[j]);
    }

    #pragma unroll
    for (int i = 0; i < 2; i++) {
        #pragma unroll
        for (int j = 0; j < 4; j++) {
            int row0 = m_base + i * 16 + g;
            int col  = n_base + j * 8 + 2 * tg;
            Y[(size_t)row0 * HH + col]           = acc[i][j][0];
            Y[(size_t)row0 * HH + col + 1]       = acc[i][j][1];
            Y[(size_t)(row0 + 8) * HH + col]     = acc[i][j][2];
            Y[(size_t)(row0 + 8) * HH + col + 1] = acc[i][j][3];
        }
    }
}

__device__ __forceinline__ float fast_tanh(float x) {
    float r;
    asm("tanh.approx.f32 %0, %1;" : "=f"(r) : "f"(x));
    return r;
}

// ---------------------------------------------------------------------------
// Score kernel: grid (t-tile, s-chunk, b), block = 128 thr (4 warps).
// Warp-per-s within a 64-wide s-chunk; 8 queries per block (enc_f row reused
// 8x from registers). Masked chunks exit immediately.
// ---------------------------------------------------------------------------
__global__ __launch_bounds__(128, 8)
void score_kernel(const int* __restrict__ src_len,
                  const float* __restrict__ v) {
    __shared__ float q_s[TQ][HH];   // 16 KB
    __shared__ float v_s[HH];       //  2 KB

    int b      = blockIdx.z;
    int s_base = blockIdx.y * SCHUNK;
    int t0     = blockIdx.x * TQ;

    int len = src_len[b];           // int32, in [1, S]
    if (s_base >= len) return;

    int tid  = threadIdx.x;
    int lane = tid & 31, warp = tid >> 5;

    {
        const float* src = g_qry_f + ((size_t)b * TT + t0) * HH;
        float* dst = &q_s[0][0];
        for (int i = tid; i < TQ * HH; i += 128) dst[i] = src[i];
        for (int h = tid; h < HH; h += 128) v_s[h] = v[h];
    }
    __syncthreads();

    int s_end = min(len, s_base + SCHUNK);

    for (int s = s_base + warp; s < s_end; s += 4) {
        const float* __restrict__ e =
            g_enc_f + ((size_t)b * SS + s) * HH + lane;
        float acc[TQ];
        #pragma unroll
        for (int tq = 0; tq < TQ; tq++) acc[tq] = 0.f;

        #pragma unroll 4
        for (int k = 0; k < 16; k++) {
            float er = e[32 * k];
            float vv = v_s[lane + 32 * k];
            #pragma unroll
            for (int tq = 0; tq < TQ; tq++)
                acc[tq] = fmaf(vv, fast_tanh(er + q_s[tq][lane + 32 * k]), acc[tq]);
        }
        #pragma unroll
        for (int o = 16; o > 0; o >>= 1) {
            #pragma unroll
            for (int tq = 0; tq < TQ; tq++)
                acc[tq] += __shfl_xor_sync(0xffffffffu, acc[tq], o);
        }
        if (lane == 0) {
            #pragma unroll
            for (int tq = 0; tq < TQ; tq++)
                g_scores[((size_t)b * TT + t0 + tq) * SS + s] = acc[tq];
        }
    }
}

// ---------------------------------------------------------------------------
// Softmax + AV: grid (t-tile, b), block = 256 thr.
// Warp-per-query softmax (8 warps == TQ), then float2 AV over enc.
// ---------------------------------------------------------------------------
__global__ __launch_bounds__(256, 4)
void softmax_av_kernel(const float* __restrict__ enc,
                       const int* __restrict__ src_len,
                       float* __restrict__ out) {
    __shared__ float w_s[TQ][SS];   // 8 KB

    int b  = blockIdx.y;
    int t0 = blockIdx.x * TQ;
    int tid = threadIdx.x;
    int lane = tid & 31, warp = tid >> 5;

    int len = src_len[b];

    // ---- softmax: warp `warp` owns query row t0+warp
    {
        const float* __restrict__ srow =
            g_scores + ((size_t)b * TT + t0 + warp) * SS;
        float vals[SS / 32];
        float m = -INFINITY;
        #pragma unroll
        for (int j = 0; j < SS / 32; j++) {
            int s = lane + 32 * j;
            float x = (s < len) ? srow[s] : -INFINITY;
            vals[j] = x;
            m = fmaxf(m, x);
        }
        #pragma unroll
        for (int o = 16; o > 0; o >>= 1)
            m = fmaxf(m, __shfl_xor_sync(0xffffffffu, m, o));
        float sum = 0.f;
        #pragma unroll
        for (int j = 0; j < SS / 32; j++) {
            int s = lane + 32 * j;
            float ex = (s < len) ? __expf(vals[j] - m) : 0.f;
            vals[j] = ex;
            sum += ex;
        }
        #pragma unroll
        for (int o = 16; o > 0; o >>= 1)
            sum += __shfl_xor_sync(0xffffffffu, sum, o);
        float inv = 1.f / sum;
        #pragma unroll
        for (int j = 0; j < SS / 32; j++)
            w_s[warp][lane + 32 * j] = vals[j] * inv;
    }
    __syncthreads();

    // ---- AV: thread owns h = 2*tid, 2*tid+1 (float2), all TQ queries
    {
        float2 acc[TQ];
        #pragma unroll
        for (int tq = 0; tq < TQ; tq++) acc[tq] = make_float2(0.f, 0.f);

        const float2* __restrict__ eb =
            (const float2*)(enc + (size_t)b * SS * HH) + tid;
        for (int s = 0; s < len; s++) {
            float2 ev = eb[(size_t)s * (HH / 2)];
            #pragma unroll
            for (int tq = 0; tq < TQ; tq++) {
                float w = w_s[tq][s];
                acc[tq].x = fmaf(w, ev.x, acc[tq].x);
                acc[tq].y = fmaf(w, ev.y, acc[tq].y);
            }
        }
        #pragma unroll
        for (int tq = 0; tq < TQ; tq++) {
            float2* op = (float2*)(out + ((size_t)b * TT + t0 + tq) * HH) + tid;
            *op = acc[tq];
        }
    }
}

extern "C" void kernel_launch(void* const* d_in, const int* in_sizes, int n_in,
                              void* d_out, int out_size) {
    const float* query   = (const float*)d_in[0];
    const float* enc     = (const float*)d_in[1];
    const int*   src_len = (const int*)d_in[2];
    const float* W_h     = (const float*)d_in[3];
    const float* W_s     = (const float*)d_in[4];
    const float* v       = (const float*)d_in[5];
    float*       out     = (float*)d_out;

    dim3 ggrd(HH / 64, (2 * BB * SS) / 128);       // (8, 32) = 256 blocks
    gemm_tf32_kernel<<<ggrd, 256>>>(enc, query, W_h, W_s);

    dim3 sgrd(TT / TQ, SS / SCHUNK, BB);           // (32, 4, 8) = 1024 blocks
    score_kernel<<<sgrd, 128>>>(src_len, v);

    dim3 agrd(TT / TQ, BB);                        // (32, 8) = 256 blocks
    softmax_av_kernel<<<agrd, 256>>>(enc, src_len, out);
}

// round 10
// speedup vs baseline: 2.5903x; 1.5161x over previous
#include <cuda_runtime.h>
#include <math.h>

#define BB 8
#define TT 256
#define SS 256
#define HH 512
#define TQ 8
#define SCHUNK 64

// Scratch (device globals — no allocation).
__device__ float g_enc_f[BB * SS * HH];
__device__ float g_qry_f[BB * TT * HH];
__device__ float g_scores[BB * TT * SS];

// ---------------------------------------------------------------------------
// tf32 helpers
// ---------------------------------------------------------------------------
__device__ __forceinline__ unsigned f2tf32(float x) {
    unsigned r;
    asm("cvt.rna.tf32.f32 %0, %1;" : "=r"(r) : "f"(x));
    return r;
}

__device__ __forceinline__ void mma_tf32(float* c, const unsigned* a, const unsigned* b) {
    asm("mma.sync.aligned.m16n8k8.row.col.f32.tf32.tf32.f32 "
        "{%0,%1,%2,%3},{%4,%5,%6,%7},{%8,%9},{%0,%1,%2,%3};"
        : "+f"(c[0]), "+f"(c[1]), "+f"(c[2]), "+f"(c[3])
        : "r"(a[0]), "r"(a[1]), "r"(a[2]), "r"(a[3]), "r"(b[0]), "r"(b[1]));
}

// ---------------------------------------------------------------------------
// Fused projection GEMM (tf32 tensor cores), smem-staged:
//   fused rows [0,2048):    g_enc_f = enc @ W_h^T
//   fused rows [2048,4096): g_qry_f = query @ W_s^T
// Block tile 128(m) x 64(n), k-chunk 16, 8 warps (4m x 2n), warp tile 32x32.
//
// Smem layout: columns permuted kperm = (k%4)*4 + (k/4), group-XOR-swizzled
// by ((row>>1)&3). A thread's 4 operand values for the two k-steps of a
// 16-chunk land in one float4 => one conflict-free LDS.128 per fragment.
// ---------------------------------------------------------------------------
__global__ __launch_bounds__(256, 2)
void gemm_tf32_kernel(const float* __restrict__ enc,
                      const float* __restrict__ qry,
                      const float* __restrict__ W_h,
                      const float* __restrict__ W_s) {
    __shared__ float A_s[128 * 16];   // 8 KB
    __shared__ float B_s[64 * 16];    // 4 KB

    int tid  = threadIdx.x;
    int lane = tid & 31, warp = tid >> 5;
    int g  = lane >> 2;          // 0..7
    int tg = lane & 3;           // 0..3
    int warp_m = warp & 3;       // 0..3
    int warp_n = warp >> 2;      // 0..1

    int m_blk = blockIdx.y * 128;        // fused row base (0..3968)
    int n_blk = blockIdx.x * 64;

    const float* X;
    const float* W;
    float*       Y;
    if (m_blk < 2048) {
        X = enc + (size_t)m_blk * HH;
        W = W_h;
        Y = g_enc_f + (size_t)m_blk * HH;
    } else {
        X = qry + (size_t)(m_blk - 2048) * HH;
        W = W_s;
        Y = g_qry_f + (size_t)(m_blk - 2048) * HH;
    }

    // Staging thread mapping (coalesced 64B rows):
    //   A: 2 float4/thread:  lin = tid + 256*i -> m = lin/4, j = lin%4
    //   B: 1 float4/thread:  n = tid/4, j = tid%4
    int am0 = tid >> 2,  aj = tid & 3;        // i=0 row
    int am1 = (tid + 256) >> 2;               // i=1 row (same j)
    int bn  = tid >> 2,  bj = tid & 3;

    const float4* Xv0 = (const float4*)(X + (size_t)am0 * HH) + aj;
    const float4* Xv1 = (const float4*)(X + (size_t)am1 * HH) + aj;
    const float4* Wv  = (const float4*)(W + (size_t)(n_blk + bn) * HH) + bj;

    int aswz0 = (am0 >> 1) & 3;
    int aswz1 = (am1 >> 1) & 3;
    int bswz  = (bn  >> 1) & 3;

    float acc[2][4][4];
    #pragma unroll
    for (int i = 0; i < 2; i++)
        #pragma unroll
        for (int jf = 0; jf < 4; jf++)
            #pragma unroll
            for (int c = 0; c < 4; c++) acc[i][jf][c] = 0.f;

    // Fragment read bases (swz depends only on (g>>1)&3: all frag-row bases
    // are multiples of 8, and 8>>1 = 4 ≡ 0 mod 4).
    int fswz = (g >> 1) & 3;
    int fcol = 4 * (tg ^ fswz);
    int a_row0 = warp_m * 32 + g;
    int b_row0 = warp_n * 32 + g;

    // Prefetch k-chunk 0
    float4 va0 = Xv0[0];
    float4 va1 = Xv1[0];
    float4 vb  = Wv[0];

    for (int k0 = 0; k0 < HH; k0 += 16) {
        // ---- stage current chunk (permuted + swizzled scatter)
        #pragma unroll
        for (int r = 0; r < 4; r++) {
            float e0 = (r == 0) ? va0.x : (r == 1) ? va0.y : (r == 2) ? va0.z : va0.w;
            float e1 = (r == 0) ? va1.x : (r == 1) ? va1.y : (r == 2) ? va1.z : va1.w;
            float e2 = (r == 0) ? vb.x  : (r == 1) ? vb.y  : (r == 2) ? vb.z  : vb.w;
            A_s[am0 * 16 + ((r ^ aswz0) << 2) + aj] = e0;
            A_s[am1 * 16 + ((r ^ aswz1) << 2) + aj] = e1;
            B_s[bn  * 16 + ((r ^ bswz)  << 2) + bj] = e2;
        }
        __syncthreads();

        // ---- prefetch next chunk: 16 floats = FOUR float4s per chunk
        if (k0 + 16 < HH) {
            va0 = Xv0[(k0 + 16) >> 2];
            va1 = Xv1[(k0 + 16) >> 2];
            vb  = Wv [(k0 + 16) >> 2];
        }

        // ---- fragments: one LDS.128 each
        float4 raf[2][2];                    // [m-frag][lo/hi row]
        #pragma unroll
        for (int i = 0; i < 2; i++) {
            raf[i][0] = *(const float4*)&A_s[(a_row0 + i * 16)     * 16 + fcol];
            raf[i][1] = *(const float4*)&A_s[(a_row0 + i * 16 + 8) * 16 + fcol];
        }
        float4 rbf[4];
        #pragma unroll
        for (int jf = 0; jf < 4; jf++)
            rbf[jf] = *(const float4*)&B_s[(b_row0 + jf * 8) * 16 + fcol];

        // ---- 16 MMAs (2 m-frags x 4 n-frags x 2 k-steps)
        #pragma unroll
        for (int i = 0; i < 2; i++) {
            unsigned a0[4] = { f2tf32(raf[i][0].x), f2tf32(raf[i][1].x),
                               f2tf32(raf[i][0].y), f2tf32(raf[i][1].y) };
            unsigned a1[4] = { f2tf32(raf[i][0].z), f2tf32(raf[i][1].z),
                               f2tf32(raf[i][0].w), f2tf32(raf[i][1].w) };
            #pragma unroll
            for (int jf = 0; jf < 4; jf++) {
                unsigned b0[2] = { f2tf32(rbf[jf].x), f2tf32(rbf[jf].y) };
                unsigned b1[2] = { f2tf32(rbf[jf].z), f2tf32(rbf[jf].w) };
                mma_tf32(acc[i][jf], a0, b0);
                mma_tf32(acc[i][jf], a1, b1);
            }
        }
        __syncthreads();
    }

    // ---- epilogue: c0:(g,2tg) c1:(g,2tg+1) c2:(g+8,2tg) c3:(g+8,2tg+1)
    #pragma unroll
    for (int i = 0; i < 2; i++) {
        #pragma unroll
        for (int jf = 0; jf < 4; jf++) {
            int row0 = warp_m * 32 + i * 16 + g;
            int col  = n_blk + warp_n * 32 + jf * 8 + 2 * tg;
            float2* p0 = (float2*)&Y[(size_t)row0 * HH + col];
            float2* p1 = (float2*)&Y[(size_t)(row0 + 8) * HH + col];
            *p0 = make_float2(acc[i][jf][0], acc[i][jf][1]);
            *p1 = make_float2(acc[i][jf][2], acc[i][jf][3]);
        }
    }
}

__device__ __forceinline__ float fast_tanh(float x) {
    float r;
    asm("tanh.approx.f32 %0, %1;" : "=f"(r) : "f"(x));
    return r;
}

// ---------------------------------------------------------------------------
// Score kernel: grid (t-tile, s-chunk, b), block = 128 thr (4 warps).
// Warp-per-s within a 64-wide s-chunk; 8 queries per block. Masked chunks
// exit immediately.
// ---------------------------------------------------------------------------
__global__ __launch_bounds__(128, 8)
void score_kernel(const int* __restrict__ src_len,
                  const float* __restrict__ v) {
    __shared__ float q_s[TQ][HH];   // 16 KB
    __shared__ float v_s[HH];       //  2 KB

    int b      = blockIdx.z;
    int s_base = blockIdx.y * SCHUNK;
    int t0     = blockIdx.x * TQ;

    int len = src_len[b];           // int32, in [1, S]
    if (s_base >= len) return;

    int tid  = threadIdx.x;
    int lane = tid & 31, warp = tid >> 5;

    {
        const float* src = g_qry_f + ((size_t)b * TT + t0) * HH;
        float* dst = &q_s[0][0];
        for (int i = tid; i < TQ * HH; i += 128) dst[i] = src[i];
        for (int h = tid; h < HH; h += 128) v_s[h] = v[h];
    }
    __syncthreads();

    int s_end = min(len, s_base + SCHUNK);

    for (int s = s_base + warp; s < s_end; s += 4) {
        const float* __restrict__ e =
            g_enc_f + ((size_t)b * SS + s) * HH + lane;
        float acc[TQ];
        #pragma unroll
        for (int tq = 0; tq < TQ; tq++) acc[tq] = 0.f;

        #pragma unroll 4
        for (int k = 0; k < 16; k++) {
            float er = e[32 * k];
            float vv = v_s[lane + 32 * k];
            #pragma unroll
            for (int tq = 0; tq < TQ; tq++)
                acc[tq] = fmaf(vv, fast_tanh(er + q_s[tq][lane + 32 * k]), acc[tq]);
        }
        #pragma unroll
        for (int o = 16; o > 0; o >>= 1) {
            #pragma unroll
            for (int tq = 0; tq < TQ; tq++)
                acc[tq] += __shfl_xor_sync(0xffffffffu, acc[tq], o);
        }
        if (lane == 0) {
            #pragma unroll
            for (int tq = 0; tq < TQ; tq++)
                g_scores[((size_t)b * TT + t0 + tq) * SS + s] = acc[tq];
        }
    }
}

// ---------------------------------------------------------------------------
// Softmax + AV: grid (t-tile, b), block = 256 thr.
// Warp-per-query softmax (8 warps == TQ), then float2 AV over enc.
// ---------------------------------------------------------------------------
__global__ __launch_bounds__(256, 4)
void softmax_av_kernel(const float* __restrict__ enc,
                       const int* __restrict__ src_len,
                       float* __restrict__ out) {
    __shared__ float w_s[TQ][SS];   // 8 KB

    int b  = blockIdx.y;
    int t0 = blockIdx.x * TQ;
    int tid = threadIdx.x;
    int lane = tid & 31, warp = tid >> 5;

    int len = src_len[b];

    // ---- softmax: warp `warp` owns query row t0+warp
    {
        const float* __restrict__ srow =
            g_scores + ((size_t)b * TT + t0 + warp) * SS;
        float vals[SS / 32];
        float m = -INFINITY;
        #pragma unroll
        for (int j = 0; j < SS / 32; j++) {
            int s = lane + 32 * j;
            float x = (s < len) ? srow[s] : -INFINITY;
            vals[j] = x;
            m = fmaxf(m, x);
        }
        #pragma unroll
        for (int o = 16; o > 0; o >>= 1)
            m = fmaxf(m, __shfl_xor_sync(0xffffffffu, m, o));
        float sum = 0.f;
        #pragma unroll
        for (int j = 0; j < SS / 32; j++) {
            int s = lane + 32 * j;
            float ex = (s < len) ? __expf(vals[j] - m) : 0.f;
            vals[j] = ex;
            sum += ex;
        }
        #pragma unroll
        for (int o = 16; o > 0; o >>= 1)
            sum += __shfl_xor_sync(0xffffffffu, sum, o);
        float inv = 1.f / sum;
        #pragma unroll
        for (int j = 0; j < SS / 32; j++)
            w_s[warp][lane + 32 * j] = vals[j] * inv;
    }
    __syncthreads();

    // ---- AV: thread owns h = 2*tid, 2*tid+1 (float2), all TQ queries
    {
        float2 acc[TQ];
        #pragma unroll
        for (int tq = 0; tq < TQ; tq++) acc[tq] = make_float2(0.f, 0.f);

        const float2* __restrict__ eb =
            (const float2*)(enc + (size_t)b * SS * HH) + tid;
        for (int s = 0; s < len; s++) {
            float2 ev = eb[(size_t)s * (HH / 2)];
            #pragma unroll
            for (int tq = 0; tq < TQ; tq++) {
                float w = w_s[tq][s];
                acc[tq].x = fmaf(w, ev.x, acc[tq].x);
                acc[tq].y = fmaf(w, ev.y, acc[tq].y);
            }
        }
        #pragma unroll
        for (int tq = 0; tq < TQ; tq++) {
            float2* op = (float2*)(out + ((size_t)b * TT + t0 + tq) * HH) + tid;
            *op = acc[tq];
        }
    }
}

extern "C" void kernel_launch(void* const* d_in, const int* in_sizes, int n_in,
                              void* d_out, int out_size) {
    const float* query   = (const float*)d_in[0];
    const float* enc     = (const float*)d_in[1];
    const int*   src_len = (const int*)d_in[2];
    const float* W_h     = (const float*)d_in[3];
    const float* W_s     = (const float*)d_in[4];
    const float* v       = (const float*)d_in[5];
    float*       out     = (float*)d_out;

    dim3 ggrd(HH / 64, (2 * BB * SS) / 128);       // (8, 32) = 256 blocks
    gemm_tf32_kernel<<<ggrd, 256>>>(enc, query, W_h, W_s);

    dim3 sgrd(TT / TQ, SS / SCHUNK, BB);           // (32, 4, 8) = 1024 blocks
    score_kernel<<<sgrd, 128>>>(src_len, v);

    dim3 agrd(TT / TQ, BB);                        // (32, 8) = 256 blocks
    softmax_av_kernel<<<agrd, 256>>>(enc, src_len, out);
}